// round 7
// baseline (speedup 1.0000x reference)
#include <cuda_runtime.h>
#include <cuda_fp16.h>
#include <cstdint>

// ---------------- static problem config ----------------
#define T 4096
#define H 1024
#define F 2048
#define E 32
#define KSEL 2
#define CAP 512
#define AUX_COEF 0.01f

// ---------------- device scratch ----------------
__device__ float  g_probs[T * E];
__device__ int    g_top1[T];
__device__ int    g_route_e[T * KSEL];
__device__ float  g_route_w[T * KSEL];
__device__ int    g_route_pos[T * KSEL];
__device__ int    g_route_keep[T * KSEL];
__device__ int    g_count[E];
__device__ __half g_buf[(size_t)E * CAP * H];
__device__ __half g_g16[(size_t)E * CAP * F];
__device__ __half g_u16[(size_t)E * CAP * F];
__device__ __half g_hid[(size_t)E * CAP * F];
__device__ float  g_y[(size_t)E * CAP * H];

// ---------------- helpers ----------------
__device__ __forceinline__ uint32_t smem_u32(const void* p) {
    uint32_t a;
    asm("{ .reg .u64 t; cvta.to.shared.u64 t, %1; cvt.u32.u64 %0, t; }" : "=r"(a) : "l"(p));
    return a;
}
__device__ __forceinline__ uint32_t packh2(float lo, float hi) {
    __half2 h = __floats2half2_rn(lo, hi);
    return *(uint32_t*)&h;
}
#define STS128(ad, a0, a1, a2, a3) \
    asm volatile("st.shared.v4.b32 [%0], {%1,%2,%3,%4};" :: "r"(ad), "r"(a0), "r"(a1), "r"(a2), "r"(a3) : "memory")
#define LDSM4(r0, r1, r2, r3, ad) \
    asm volatile("ldmatrix.sync.aligned.m8n8.x4.shared.b16 {%0,%1,%2,%3}, [%4];" \
        : "=r"(r0), "=r"(r1), "=r"(r2), "=r"(r3) : "r"(ad))
#define MMA16(d, a, b0v, b1v) \
    asm volatile("mma.sync.aligned.m16n8k16.row.col.f32.f16.f16.f32 " \
        "{%0,%1,%2,%3}, {%4,%5,%6,%7}, {%8,%9}, {%0,%1,%2,%3};" \
        : "+f"(d[0]), "+f"(d[1]), "+f"(d[2]), "+f"(d[3]) \
        : "r"(a[0]), "r"(a[1]), "r"(a[2]), "r"(a[3]), "r"(b0v), "r"(b1v))
#define CP16(dst, src) \
    asm volatile("cp.async.cg.shared.global [%0], [%1], 16;" :: "r"(dst), "l"(src) : "memory")
#define CP_COMMIT() asm volatile("cp.async.commit_group;" ::: "memory")
#define CP_WAIT0()  asm volatile("cp.async.wait_group 0;" ::: "memory")

// 64B-row swizzle: physical 16B-chunk = c ^ ((row>>1)&3)
__device__ __forceinline__ uint32_t sw64(uint32_t row, uint32_t c) {
    return row * 64 + ((c ^ ((row >> 1) & 3)) * 16);
}

// ---------------- router ----------------
__global__ void router_kernel(const float* __restrict__ x,
                              const float* __restrict__ Wr,
                              const float* __restrict__ br) {
    int t = blockIdx.x;
    __shared__ float xs[H];
    __shared__ float sl[E];
    int tid = threadIdx.x;
    for (int h = tid; h < H; h += 256) xs[h] = x[(size_t)t * H + h];
    __syncthreads();
    int e = tid >> 3, r = tid & 7;
    float acc = 0.f;
    const float* w = Wr + (size_t)e * H;
    for (int h = r; h < H; h += 8) acc += xs[h] * w[h];
    acc += __shfl_down_sync(0xffffffffu, acc, 4, 8);
    acc += __shfl_down_sync(0xffffffffu, acc, 2, 8);
    acc += __shfl_down_sync(0xffffffffu, acc, 1, 8);
    if (r == 0) sl[e] = acc + br[e];
    __syncthreads();
    if (tid < 32) {
        float l = sl[tid];
        float m = l;
        #pragma unroll
        for (int o = 16; o; o >>= 1) m = fmaxf(m, __shfl_xor_sync(0xffffffffu, m, o));
        float p = __expf(l - m);
        float s = p;
        #pragma unroll
        for (int o = 16; o; o >>= 1) s += __shfl_xor_sync(0xffffffffu, s, o);
        p = p / s;
        g_probs[(size_t)t * E + tid] = p;
        float p1 = p; int i1 = tid;
        #pragma unroll
        for (int o = 16; o; o >>= 1) {
            float op = __shfl_xor_sync(0xffffffffu, p1, o);
            int   oi = __shfl_xor_sync(0xffffffffu, i1, o);
            if (op > p1 || (op == p1 && oi < i1)) { p1 = op; i1 = oi; }
        }
        float pm = (tid == i1) ? -1.f : p;
        float p2 = pm; int i2 = tid;
        #pragma unroll
        for (int o = 16; o; o >>= 1) {
            float op = __shfl_xor_sync(0xffffffffu, p2, o);
            int   oi = __shfl_xor_sync(0xffffffffu, i2, o);
            if (op > p2 || (op == p2 && oi < i2)) { p2 = op; i2 = oi; }
        }
        if (tid == 0) {
            g_top1[t] = i1;
            float mx = fmaxf(p1, p2);
            float e1 = __expf(p1 - mx), e2 = __expf(p2 - mx);
            float inv = 1.f / (e1 + e2);
            g_route_e[2 * t]     = i1; g_route_w[2 * t]     = e1 * inv;
            g_route_e[2 * t + 1] = i2; g_route_w[2 * t + 1] = e2 * inv;
        }
    }
}

// ---------------- dispatch ----------------
__global__ void dispatch_kernel() {
    __shared__ int se[T * KSEL];
    int tid = threadIdx.x;
    for (int i = tid; i < T * KSEL; i += 1024) se[i] = g_route_e[i];
    __syncthreads();
    int warp = tid >> 5, lane = tid & 31;
    int base = 0;
    for (int c = 0; c < T * KSEL; c += 32) {
        int e = se[c + lane];
        unsigned m = __ballot_sync(0xffffffffu, e == warp);
        if (e == warp) {
            int pos = base + __popc(m & ((1u << lane) - 1u));
            g_route_pos[c + lane]  = pos;
            g_route_keep[c + lane] = (pos < CAP) ? 1 : 0;
        }
        base += __popc(m);
    }
    if (lane == 0) g_count[warp] = (base < CAP) ? base : CAP;
}

// ---------------- gather ----------------
__global__ void gather_kernel(const float* __restrict__ x) {
    int i = blockIdx.x;
    if (!g_route_keep[i]) return;
    int t = i >> 1;
    int e = g_route_e[i], pos = g_route_pos[i];
    __half* dst = g_buf + ((size_t)e * CAP + pos) * H;
    const float* src = x + (size_t)t * H;
    int h = threadIdx.x * 4;
    float4 v = *(const float4*)(src + h);
    uint2 o;
    o.x = packh2(v.x, v.y);
    o.y = packh2(v.z, v.w);
    *(uint2*)(dst + h) = o;
}

// ---------------- fp16 mma.sync GEMMs ----------------
// 256 thr / 8 warps (2m x 4n), warp tile 64x64, block 128(M) x 256(N), KCH=32.
// Smem rows: 32 halves = 64B; swizzle sw64 (chunk ^= (row>>1)&3).
#define KCH 32
#define AST (128 * 64)    // 8KB
#define BST (256 * 64)    // 16KB
#define STG (AST + BST)   // 24KB/stage

// generic core: A [Mrows x Klen] fp16 (lda halves), B = W f32 [Klen x Nw] (ldb floats)
// C warp 64x64, fp16 or f32 out handled by caller-specific epilogue.
__global__ void __launch_bounds__(256, 1) gu_mma(const float* __restrict__ Wg,
                                                 const float* __restrict__ Wu) {
    extern __shared__ char smem[];
    int e = blockIdx.z, cnt = g_count[e];
    int m0 = blockIdx.y * 128;
    if (m0 >= cnt) return;
    int bx = blockIdx.x;
    const float* W = (bx < 8) ? Wg : Wu;
    __half* O = ((bx < 8) ? g_g16 : g_u16) + (size_t)e * CAP * F;
    int n0 = (bx & 7) * 256;
    uint32_t sbuf = (smem_u32(smem) + 127u) & ~127u;

    int tid = threadIdx.x, lane = tid & 31, wid = tid >> 5;
    int wm = wid >> 2, wn = wid & 3;

    const __half* A = g_buf + (size_t)e * CAP * H + (size_t)m0 * H;
    const float*  Wb = W + (size_t)e * H * F + n0;

    int crow = tid >> 1, cc = (tid & 1) * 2;   // A cp.async: row, chunk pair
    int brow = tid;                            // B: one n-row per thread
    uint32_t a_r = wm * 64 + (lane & 15);
    uint32_t b_r = wn * 64 + (lane & 15);
    uint32_t chi = (lane >> 4);                // chunk offset from lane

    float acc[4][8][4] = {};
    uint32_t rbh[16];

    const int NS = H / KCH;   // 32
    {   // prologue stage 0
        uint32_t SA = sbuf, SB = SA + AST;
        CP16(SA + sw64(crow, cc),     A + (size_t)crow * H + cc * 8);
        CP16(SA + sw64(crow, cc + 1), A + (size_t)crow * H + cc * 8 + 8);
        CP_COMMIT();
        const float* Wp = Wb + brow;
        #pragma unroll
        for (int q = 0; q < 16; q++)
            rbh[q] = packh2(Wp[(size_t)(2 * q) * F], Wp[(size_t)(2 * q + 1) * F]);
        #pragma unroll
        for (int c = 0; c < 4; c++)
            STS128(SB + sw64(brow, c), rbh[4*c], rbh[4*c+1], rbh[4*c+2], rbh[4*c+3]);
        CP_WAIT0();
        __syncthreads();
    }

    for (int s = 0; s < NS; s++) {
        if (s + 1 < NS) {
            int k0 = (s + 1) * KCH;
            uint32_t SA = sbuf + ((s + 1) & 1) * STG;
            CP16(SA + sw64(crow, cc),     A + (size_t)crow * H + k0 + cc * 8);
            CP16(SA + sw64(crow, cc + 1), A + (size_t)crow * H + k0 + cc * 8 + 8);
            CP_COMMIT();
            const float* Wp = Wb + (size_t)k0 * F + brow;
            #pragma unroll
            for (int q = 0; q < 16; q++)
                rbh[q] = packh2(Wp[(size_t)(2 * q) * F], Wp[(size_t)(2 * q + 1) * F]);
        }
        {
            uint32_t SA = sbuf + (s & 1) * STG, SB = SA + AST;
            #pragma unroll
            for (int ks = 0; ks < 2; ks++) {
                uint32_t a[4][4], bq[4][4];
                #pragma unroll
                for (int i = 0; i < 4; i++) {
                    uint32_t row = a_r + i * 16;
                    LDSM4(a[i][0], a[i][1], a[i][2], a[i][3], SA + sw64(row, 2 * ks + chi));
                }
                #pragma unroll
                for (int j = 0; j < 4; j++) {
                    uint32_t row = b_r + j * 16;
                    LDSM4(bq[j][0], bq[j][1], bq[j][2], bq[j][3], SB + sw64(row, 2 * ks + chi));
                }
                #pragma unroll
                for (int i = 0; i < 4; i++)
                    #pragma unroll
                    for (int j8 = 0; j8 < 8; j8++)
                        MMA16(acc[i][j8], a[i], bq[j8 >> 1][j8 & 1], bq[j8 >> 1][(j8 & 1) + 2]);
            }
        }
        if (s + 1 < NS) {
            uint32_t SB = sbuf + ((s + 1) & 1) * STG + AST;
            #pragma unroll
            for (int c = 0; c < 4; c++)
                STS128(SB + sw64(brow, c), rbh[4*c], rbh[4*c+1], rbh[4*c+2], rbh[4*c+3]);
        }
        CP_WAIT0();
        __syncthreads();
    }

    int r0 = m0 + wm * 64 + (lane >> 2);
    int c0 = n0 + wn * 64 + (lane & 3) * 2;
    #pragma unroll
    for (int i = 0; i < 4; i++) {
        #pragma unroll
        for (int j8 = 0; j8 < 8; j8++) {
            int r = r0 + i * 16, c = c0 + j8 * 8;
            if (r < cnt)
                *(uint32_t*)(O + (size_t)r * F + c) = packh2(acc[i][j8][0], acc[i][j8][1]);
            if (r + 8 < cnt)
                *(uint32_t*)(O + (size_t)(r + 8) * F + c) = packh2(acc[i][j8][2], acc[i][j8][3]);
        }
    }
}

// ---------------- activation ----------------
__global__ void act_kernel() {
    size_t i = ((size_t)blockIdx.x * 256 + threadIdx.x) * 8;
    uint4 gv = *(const uint4*)(g_g16 + i);
    uint4 uv = *(const uint4*)(g_u16 + i);
    const uint32_t* gp = (const uint32_t*)&gv;
    const uint32_t* up = (const uint32_t*)&uv;
    uint4 ov;
    uint32_t* op = (uint32_t*)&ov;
    #pragma unroll
    for (int q = 0; q < 4; q++) {
        float2 g2 = __half22float2(*(const __half2*)&gp[q]);
        float2 u2 = __half22float2(*(const __half2*)&up[q]);
        op[q] = packh2(g2.x / (1.f + __expf(-g2.x)) * u2.x,
                       g2.y / (1.f + __expf(-g2.y)) * u2.y);
    }
    *(uint4*)(g_hid + i) = ov;
}

// ---------------- down GEMM ----------------
__global__ void __launch_bounds__(256, 1) down_mma(const float* __restrict__ Wd) {
    extern __shared__ char smem[];
    int e = blockIdx.z, cnt = g_count[e];
    int m0 = blockIdx.y * 128;
    if (m0 >= cnt) return;
    int n0 = blockIdx.x * 256;
    uint32_t sbuf = (smem_u32(smem) + 127u) & ~127u;

    int tid = threadIdx.x, lane = tid & 31, wid = tid >> 5;
    int wm = wid >> 2, wn = wid & 3;

    const __half* A = g_hid + ((size_t)e * CAP + m0) * F;
    const float*  Wb = Wd + (size_t)e * F * H + n0;

    int crow = tid >> 1, cc = (tid & 1) * 2;
    int brow = tid;
    uint32_t a_r = wm * 64 + (lane & 15);
    uint32_t b_r = wn * 64 + (lane & 15);
    uint32_t chi = (lane >> 4);

    float acc[4][8][4] = {};
    uint32_t rbh[16];

    const int NS = F / KCH;   // 64
    {
        uint32_t SA = sbuf, SB = SA + AST;
        CP16(SA + sw64(crow, cc),     A + (size_t)crow * F + cc * 8);
        CP16(SA + sw64(crow, cc + 1), A + (size_t)crow * F + cc * 8 + 8);
        CP_COMMIT();
        const float* Wp = Wb + brow;
        #pragma unroll
        for (int q = 0; q < 16; q++)
            rbh[q] = packh2(Wp[(size_t)(2 * q) * H], Wp[(size_t)(2 * q + 1) * H]);
        #pragma unroll
        for (int c = 0; c < 4; c++)
            STS128(SB + sw64(brow, c), rbh[4*c], rbh[4*c+1], rbh[4*c+2], rbh[4*c+3]);
        CP_WAIT0();
        __syncthreads();
    }

    for (int s = 0; s < NS; s++) {
        if (s + 1 < NS) {
            int k0 = (s + 1) * KCH;
            uint32_t SA = sbuf + ((s + 1) & 1) * STG;
            CP16(SA + sw64(crow, cc),     A + (size_t)crow * F + k0 + cc * 8);
            CP16(SA + sw64(crow, cc + 1), A + (size_t)crow * F + k0 + cc * 8 + 8);
            CP_COMMIT();
            const float* Wp = Wb + (size_t)k0 * H + brow;
            #pragma unroll
            for (int q = 0; q < 16; q++)
                rbh[q] = packh2(Wp[(size_t)(2 * q) * H], Wp[(size_t)(2 * q + 1) * H]);
        }
        {
            uint32_t SA = sbuf + (s & 1) * STG, SB = SA + AST;
            #pragma unroll
            for (int ks = 0; ks < 2; ks++) {
                uint32_t a[4][4], bq[4][4];
                #pragma unroll
                for (int i = 0; i < 4; i++) {
                    uint32_t row = a_r + i * 16;
                    LDSM4(a[i][0], a[i][1], a[i][2], a[i][3], SA + sw64(row, 2 * ks + chi));
                }
                #pragma unroll
                for (int j = 0; j < 4; j++) {
                    uint32_t row = b_r + j * 16;
                    LDSM4(bq[j][0], bq[j][1], bq[j][2], bq[j][3], SB + sw64(row, 2 * ks + chi));
                }
                #pragma unroll
                for (int i = 0; i < 4; i++)
                    #pragma unroll
                    for (int j8 = 0; j8 < 8; j8++)
                        MMA16(acc[i][j8], a[i], bq[j8 >> 1][j8 & 1], bq[j8 >> 1][(j8 & 1) + 2]);
            }
        }
        if (s + 1 < NS) {
            uint32_t SB = sbuf + ((s + 1) & 1) * STG + AST;
            #pragma unroll
            for (int c = 0; c < 4; c++)
                STS128(SB + sw64(brow, c), rbh[4*c], rbh[4*c+1], rbh[4*c+2], rbh[4*c+3]);
        }
        CP_WAIT0();
        __syncthreads();
    }

    float* Y = g_y + (size_t)e * CAP * H;
    int r0 = m0 + wm * 64 + (lane >> 2);
    int c0 = n0 + wn * 64 + (lane & 3) * 2;
    #pragma unroll
    for (int i = 0; i < 4; i++) {
        #pragma unroll
        for (int j8 = 0; j8 < 8; j8++) {
            int r = r0 + i * 16, c = c0 + j8 * 8;
            if (r < cnt)
                *(float2*)(Y + (size_t)r * H + c) = make_float2(acc[i][j8][0], acc[i][j8][1]);
            if (r + 8 < cnt)
                *(float2*)(Y + (size_t)(r + 8) * H + c) = make_float2(acc[i][j8][2], acc[i][j8][3]);
        }
    }
}

// ---------------- combine ----------------
__global__ void combine_kernel(float* __restrict__ out) {
    int t = blockIdx.x;
    int i0 = 2 * t, i1 = 2 * t + 1;
    int e0 = g_route_e[i0], e1 = g_route_e[i1];
    int k0 = g_route_keep[i0], k1 = g_route_keep[i1];
    int p0 = k0 ? g_route_pos[i0] : 0;
    int p1 = k1 ? g_route_pos[i1] : 0;
    float w0 = k0 ? g_route_w[i0] : 0.f;
    float w1 = k1 ? g_route_w[i1] : 0.f;
    const float* y0 = g_y + ((size_t)e0 * CAP + p0) * H;
    const float* y1 = g_y + ((size_t)e1 * CAP + p1) * H;
    float* o = out + (size_t)t * H;
    int h = threadIdx.x * 4;
    float4 a = *(const float4*)(y0 + h);
    float4 b = *(const float4*)(y1 + h);
    float4 r;
    r.x = w0 * a.x + w1 * b.x;
    r.y = w0 * a.y + w1 * b.y;
    r.z = w0 * a.z + w1 * b.z;
    r.w = w0 * a.w + w1 * b.w;
    *(float4*)(o + h) = r;
}

// ---------------- aux loss ----------------
__global__ void aux_kernel(float* __restrict__ out_aux) {
    int e = threadIdx.x >> 5, lane = threadIdx.x & 31;
    float s = 0.f; int c = 0;
    for (int t = lane; t < T; t += 32) {
        s += g_probs[(size_t)t * E + e];
        c += (g_top1[t] == e) ? 1 : 0;
    }
    #pragma unroll
    for (int o = 16; o; o >>= 1) {
        s += __shfl_xor_sync(0xffffffffu, s, o);
        c += __shfl_xor_sync(0xffffffffu, c, o);
    }
    __shared__ float part[E];
    if (lane == 0) part[e] = (s / (float)T) * ((float)c / (float)T);
    __syncthreads();
    if (threadIdx.x == 0) {
        float a = 0.f;
        for (int i = 0; i < E; i++) a += part[i];
        *out_aux = a * (float)E * AUX_COEF;
    }
}

// ---------------- launch ----------------
extern "C" void kernel_launch(void* const* d_in, const int* in_sizes, int n_in,
                              void* d_out, int out_size) {
    const float* x  = (const float*)d_in[0];
    const float* Wr = (const float*)d_in[1];
    const float* br = (const float*)d_in[2];
    const float* Wg = (const float*)d_in[3];
    const float* Wu = (const float*)d_in[4];
    const float* Wd = (const float*)d_in[5];
    float* out = (float*)d_out;

    int smem = 2 * STG + 128;   // 48KB + pad
    cudaFuncSetAttribute(gu_mma, cudaFuncAttributeMaxDynamicSharedMemorySize, smem);
    cudaFuncSetAttribute(down_mma, cudaFuncAttributeMaxDynamicSharedMemorySize, smem);

    router_kernel<<<T, 256>>>(x, Wr, br);
    dispatch_kernel<<<1, 1024>>>();
    gather_kernel<<<T * KSEL, 256>>>(x);

    dim3 gu_grid(16, CAP / 128, E);          // 8 G n-tiles + 8 U n-tiles
    gu_mma<<<gu_grid, 256, smem>>>(Wg, Wu);

    act_kernel<<<(int)(((size_t)E * CAP * F) / 2048), 256>>>();

    dim3 dn_grid(H / 256, CAP / 128, E);
    down_mma<<<dn_grid, 256, smem>>>(Wd);

    combine_kernel<<<T, 256>>>(out);

    if (out_size > T * H)
        aux_kernel<<<1, 1024>>>(out + (size_t)T * H);
}

// round 8
// speedup vs baseline: 1.2252x; 1.2252x over previous
#include <cuda_runtime.h>
#include <cuda_fp16.h>
#include <cstdint>

// ---------------- static problem config ----------------
#define T 4096
#define H 1024
#define F 2048
#define E 32
#define KSEL 2
#define CAP 512
#define AUX_COEF 0.01f

// ---------------- device scratch ----------------
__device__ float  g_probs[T * E];
__device__ int    g_top1[T];
__device__ int    g_route_e[T * KSEL];
__device__ float  g_route_w[T * KSEL];
__device__ int    g_route_pos[T * KSEL];
__device__ int    g_route_keep[T * KSEL];
__device__ int    g_count[E];
__device__ __half g_buf[(size_t)E * CAP * H];
__device__ __half g_hid[(size_t)E * CAP * F];
__device__ float  g_y[(size_t)E * CAP * H];

// ---------------- helpers ----------------
__device__ __forceinline__ uint32_t smem_u32(const void* p) {
    uint32_t a;
    asm("{ .reg .u64 t; cvta.to.shared.u64 t, %1; cvt.u32.u64 %0, t; }" : "=r"(a) : "l"(p));
    return a;
}
__device__ __forceinline__ uint32_t packh2(float lo, float hi) {
    __half2 h = __floats2half2_rn(lo, hi);
    return *(uint32_t*)&h;
}
#define STS128(ad, a0, a1, a2, a3) \
    asm volatile("st.shared.v4.b32 [%0], {%1,%2,%3,%4};" :: "r"(ad), "r"(a0), "r"(a1), "r"(a2), "r"(a3) : "memory")
#define LDSM4(r0, r1, r2, r3, ad) \
    asm volatile("ldmatrix.sync.aligned.m8n8.x4.shared.b16 {%0,%1,%2,%3}, [%4];" \
        : "=r"(r0), "=r"(r1), "=r"(r2), "=r"(r3) : "r"(ad))
#define MMA16(d, a, b0v, b1v) \
    asm volatile("mma.sync.aligned.m16n8k16.row.col.f32.f16.f16.f32 " \
        "{%0,%1,%2,%3}, {%4,%5,%6,%7}, {%8,%9}, {%0,%1,%2,%3};" \
        : "+f"(d[0]), "+f"(d[1]), "+f"(d[2]), "+f"(d[3]) \
        : "r"(a[0]), "r"(a[1]), "r"(a[2]), "r"(a[3]), "r"(b0v), "r"(b1v))
#define CP16(dst, src) \
    asm volatile("cp.async.cg.shared.global [%0], [%1], 16;" :: "r"(dst), "l"(src) : "memory")
#define CP_COMMIT() asm volatile("cp.async.commit_group;" ::: "memory")
#define CP_WAIT0()  asm volatile("cp.async.wait_group 0;" ::: "memory")

// 256B-row swizzle: 16 chunks of 16B; phys chunk = c ^ (row & 7) (bit3 preserved)
__device__ __forceinline__ uint32_t sw256(uint32_t row, uint32_t c) {
    return row * 256 + ((c ^ (row & 7)) * 16);
}

// ---------------- router ----------------
__global__ void router_kernel(const float* __restrict__ x,
                              const float* __restrict__ Wr,
                              const float* __restrict__ br) {
    int t = blockIdx.x;
    __shared__ float xs[H];
    __shared__ float sl[E];
    int tid = threadIdx.x;
    for (int h = tid; h < H; h += 256) xs[h] = x[(size_t)t * H + h];
    __syncthreads();
    int e = tid >> 3, r = tid & 7;
    float acc = 0.f;
    const float* w = Wr + (size_t)e * H;
    for (int h = r; h < H; h += 8) acc += xs[h] * w[h];
    acc += __shfl_down_sync(0xffffffffu, acc, 4, 8);
    acc += __shfl_down_sync(0xffffffffu, acc, 2, 8);
    acc += __shfl_down_sync(0xffffffffu, acc, 1, 8);
    if (r == 0) sl[e] = acc + br[e];
    __syncthreads();
    if (tid < 32) {
        float l = sl[tid];
        float m = l;
        #pragma unroll
        for (int o = 16; o; o >>= 1) m = fmaxf(m, __shfl_xor_sync(0xffffffffu, m, o));
        float p = __expf(l - m);
        float s = p;
        #pragma unroll
        for (int o = 16; o; o >>= 1) s += __shfl_xor_sync(0xffffffffu, s, o);
        p = p / s;
        g_probs[(size_t)t * E + tid] = p;
        float p1 = p; int i1 = tid;
        #pragma unroll
        for (int o = 16; o; o >>= 1) {
            float op = __shfl_xor_sync(0xffffffffu, p1, o);
            int   oi = __shfl_xor_sync(0xffffffffu, i1, o);
            if (op > p1 || (op == p1 && oi < i1)) { p1 = op; i1 = oi; }
        }
        float pm = (tid == i1) ? -1.f : p;
        float p2 = pm; int i2 = tid;
        #pragma unroll
        for (int o = 16; o; o >>= 1) {
            float op = __shfl_xor_sync(0xffffffffu, p2, o);
            int   oi = __shfl_xor_sync(0xffffffffu, i2, o);
            if (op > p2 || (op == p2 && oi < i2)) { p2 = op; i2 = oi; }
        }
        if (tid == 0) {
            g_top1[t] = i1;
            float mx = fmaxf(p1, p2);
            float e1 = __expf(p1 - mx), e2 = __expf(p2 - mx);
            float inv = 1.f / (e1 + e2);
            g_route_e[2 * t]     = i1; g_route_w[2 * t]     = e1 * inv;
            g_route_e[2 * t + 1] = i2; g_route_w[2 * t + 1] = e2 * inv;
        }
    }
}

// ---------------- dispatch ----------------
__global__ void dispatch_kernel() {
    __shared__ int se[T * KSEL];
    int tid = threadIdx.x;
    for (int i = tid; i < T * KSEL; i += 1024) se[i] = g_route_e[i];
    __syncthreads();
    int warp = tid >> 5, lane = tid & 31;
    int base = 0;
    for (int c = 0; c < T * KSEL; c += 32) {
        int e = se[c + lane];
        unsigned m = __ballot_sync(0xffffffffu, e == warp);
        if (e == warp) {
            int pos = base + __popc(m & ((1u << lane) - 1u));
            g_route_pos[c + lane]  = pos;
            g_route_keep[c + lane] = (pos < CAP) ? 1 : 0;
        }
        base += __popc(m);
    }
    if (lane == 0) g_count[warp] = (base < CAP) ? base : CAP;
}

// ---------------- gather ----------------
__global__ void gather_kernel(const float* __restrict__ x) {
    int i = blockIdx.x;
    if (!g_route_keep[i]) return;
    int t = i >> 1;
    int e = g_route_e[i], pos = g_route_pos[i];
    __half* dst = g_buf + ((size_t)e * CAP + pos) * H;
    const float* src = x + (size_t)t * H;
    int h = threadIdx.x * 4;
    float4 v = *(const float4*)(src + h);
    uint2 o;
    o.x = packh2(v.x, v.y);
    o.y = packh2(v.z, v.w);
    *(uint2*)(dst + h) = o;
}

// ---------------- fused gate/up GEMM + SwiGLU (fp16 mma.sync) ----------------
// Block 128(M)x128(N), 512 thr / 16 warps (4m x 4n), warp 32x32 per matrix (G and U).
// KCH=128 halves/stage; smem rows 256B; swizzle sw256.
#define KCH 128
#define GU_AST (128 * 256)           // 32KB per tile (A, BG, BU each)
#define GU_STG (3 * GU_AST)          // 96KB/stage
#define DN_AST (256 * 256)           // 64KB
#define DN_BST (128 * 256)           // 32KB
#define DN_STG (DN_AST + DN_BST)     // 96KB/stage

__global__ void __launch_bounds__(512, 1) gu_mma(const float* __restrict__ Wg,
                                                 const float* __restrict__ Wu) {
    extern __shared__ char smem[];
    int e = blockIdx.z, cnt = g_count[e];
    int m0 = blockIdx.y * 128;
    if (m0 >= cnt) return;
    int n0 = blockIdx.x * 128;
    uint32_t sbuf = (smem_u32(smem) + 127u) & ~127u;

    int tid = threadIdx.x, lane = tid & 31, wid = tid >> 5;
    int wm = wid >> 2, wn = wid & 3;

    const __half* A = g_buf + (size_t)e * CAP * H + (size_t)m0 * H;
    const float* G = Wg + (size_t)e * H * F + n0;
    const float* U = Wu + (size_t)e * H * F + n0;

    int crow = tid >> 2, cbase = (tid & 3) * 4;   // A: row, 4 chunks
    int bn = tid & 127, kh = tid >> 7;            // B: n-row, k-quarter (32 k's)
    uint32_t a_r = wm * 32 + (lane & 15);
    uint32_t b_r = wn * 32 + (lane & 15);
    uint32_t chi = lane >> 4;

    float accG[2][4][4] = {};
    float accU[2][4][4] = {};
    uint32_t rb[16];

    const int NS = H / KCH;   // 8
    // ---- prologue: stage 0 ----
    {
        uint32_t SA = sbuf, SBG = SA + GU_AST, SBU = SBG + GU_AST;
        #pragma unroll
        for (int q = 0; q < 4; q++)
            CP16(SA + sw256(crow, cbase + q), A + (size_t)crow * H + (cbase + q) * 8);
        CP_COMMIT();
        #pragma unroll
        for (int q = 0; q < 16; q++)
            rb[q] = packh2(G[(size_t)(kh * 32 + 2 * q) * F + bn], G[(size_t)(kh * 32 + 2 * q + 1) * F + bn]);
        #pragma unroll
        for (int c = 0; c < 4; c++)
            STS128(SBG + sw256(bn, kh * 4 + c), rb[4*c], rb[4*c+1], rb[4*c+2], rb[4*c+3]);
        #pragma unroll
        for (int q = 0; q < 16; q++)
            rb[q] = packh2(U[(size_t)(kh * 32 + 2 * q) * F + bn], U[(size_t)(kh * 32 + 2 * q + 1) * F + bn]);
        #pragma unroll
        for (int c = 0; c < 4; c++)
            STS128(SBU + sw256(bn, kh * 4 + c), rb[4*c], rb[4*c+1], rb[4*c+2], rb[4*c+3]);
        CP_WAIT0();
        __syncthreads();
    }

    for (int s = 0; s < NS; s++) {
        uint32_t SA = sbuf + (s & 1) * GU_STG;
        uint32_t SBG = SA + GU_AST, SBU = SBG + GU_AST;
        uint32_t SAn = sbuf + ((s + 1) & 1) * GU_STG;
        uint32_t SBGn = SAn + GU_AST, SBUn = SBGn + GU_AST;
        int k0 = (s + 1) * KCH;

        if (s + 1 < NS) {
            #pragma unroll
            for (int q = 0; q < 4; q++)
                CP16(SAn + sw256(crow, cbase + q), A + (size_t)crow * H + k0 + (cbase + q) * 8);
            CP_COMMIT();
            #pragma unroll
            for (int q = 0; q < 16; q++)
                rb[q] = packh2(G[(size_t)(k0 + kh * 32 + 2 * q) * F + bn], G[(size_t)(k0 + kh * 32 + 2 * q + 1) * F + bn]);
        }
        // compute ks 0..3
        #pragma unroll
        for (int ks = 0; ks < 4; ks++) {
            uint32_t a[2][4], bg[2][4], bu[2][4];
            #pragma unroll
            for (int i = 0; i < 2; i++)
                LDSM4(a[i][0], a[i][1], a[i][2], a[i][3], SA + sw256(a_r + i * 16, ks * 2 + chi));
            #pragma unroll
            for (int j = 0; j < 2; j++) {
                LDSM4(bg[j][0], bg[j][1], bg[j][2], bg[j][3], SBG + sw256(b_r + j * 16, ks * 2 + chi));
                LDSM4(bu[j][0], bu[j][1], bu[j][2], bu[j][3], SBU + sw256(b_r + j * 16, ks * 2 + chi));
            }
            #pragma unroll
            for (int i = 0; i < 2; i++)
                #pragma unroll
                for (int j4 = 0; j4 < 4; j4++) {
                    MMA16(accG[i][j4], a[i], bg[j4 >> 1][j4 & 1], bg[j4 >> 1][(j4 & 1) + 2]);
                    MMA16(accU[i][j4], a[i], bu[j4 >> 1][j4 & 1], bu[j4 >> 1][(j4 & 1) + 2]);
                }
        }
        if (s + 1 < NS) {
            #pragma unroll
            for (int c = 0; c < 4; c++)
                STS128(SBGn + sw256(bn, kh * 4 + c), rb[4*c], rb[4*c+1], rb[4*c+2], rb[4*c+3]);
            #pragma unroll
            for (int q = 0; q < 16; q++)
                rb[q] = packh2(U[(size_t)(k0 + kh * 32 + 2 * q) * F + bn], U[(size_t)(k0 + kh * 32 + 2 * q + 1) * F + bn]);
        }
        // compute ks 4..7
        #pragma unroll
        for (int ks = 4; ks < 8; ks++) {
            uint32_t a[2][4], bg[2][4], bu[2][4];
            #pragma unroll
            for (int i = 0; i < 2; i++)
                LDSM4(a[i][0], a[i][1], a[i][2], a[i][3], SA + sw256(a_r + i * 16, ks * 2 + chi));
            #pragma unroll
            for (int j = 0; j < 2; j++) {
                LDSM4(bg[j][0], bg[j][1], bg[j][2], bg[j][3], SBG + sw256(b_r + j * 16, ks * 2 + chi));
                LDSM4(bu[j][0], bu[j][1], bu[j][2], bu[j][3], SBU + sw256(b_r + j * 16, ks * 2 + chi));
            }
            #pragma unroll
            for (int i = 0; i < 2; i++)
                #pragma unroll
                for (int j4 = 0; j4 < 4; j4++) {
                    MMA16(accG[i][j4], a[i], bg[j4 >> 1][j4 & 1], bg[j4 >> 1][(j4 & 1) + 2]);
                    MMA16(accU[i][j4], a[i], bu[j4 >> 1][j4 & 1], bu[j4 >> 1][(j4 & 1) + 2]);
                }
        }
        if (s + 1 < NS) {
            #pragma unroll
            for (int c = 0; c < 4; c++)
                STS128(SBUn + sw256(bn, kh * 4 + c), rb[4*c], rb[4*c+1], rb[4*c+2], rb[4*c+3]);
        }
        CP_WAIT0();
        __syncthreads();
    }

    // epilogue: silu(g)*u -> g_hid (fp16)
    __half* Hd = g_hid + (size_t)e * CAP * F;
    int r0 = m0 + wm * 32 + (lane >> 2);
    int c0 = n0 + wn * 32 + (lane & 3) * 2;
    #pragma unroll
    for (int i = 0; i < 2; i++) {
        #pragma unroll
        for (int j = 0; j < 4; j++) {
            int r = r0 + i * 16, c = c0 + j * 8;
            if (r < cnt) {
                float g0 = accG[i][j][0], g1 = accG[i][j][1];
                *(uint32_t*)(Hd + (size_t)r * F + c) =
                    packh2(g0 / (1.f + __expf(-g0)) * accU[i][j][0],
                           g1 / (1.f + __expf(-g1)) * accU[i][j][1]);
            }
            if (r + 8 < cnt) {
                float g2 = accG[i][j][2], g3 = accG[i][j][3];
                *(uint32_t*)(Hd + (size_t)(r + 8) * F + c) =
                    packh2(g2 / (1.f + __expf(-g2)) * accU[i][j][2],
                           g3 / (1.f + __expf(-g3)) * accU[i][j][3]);
            }
        }
    }
}

// ---------------- down GEMM: y = hid16 @ Wd ----------------
// Block 256(M)x128(N), 512 thr / 16 warps (4m x 4n), warp 64x32, KCH=128.
__global__ void __launch_bounds__(512, 1) down_mma(const float* __restrict__ Wd) {
    extern __shared__ char smem[];
    int e = blockIdx.z, cnt = g_count[e];
    int m0 = blockIdx.y * 256;
    if (m0 >= cnt) return;
    int n0 = blockIdx.x * 128;
    uint32_t sbuf = (smem_u32(smem) + 127u) & ~127u;

    int tid = threadIdx.x, lane = tid & 31, wid = tid >> 5;
    int wm = wid >> 2, wn = wid & 3;

    const __half* A = g_hid + ((size_t)e * CAP + m0) * F;
    const float*  W = Wd + (size_t)e * F * H + n0;

    int crow = tid >> 1, cbase = (tid & 1) * 8;   // A: row, 8 chunks
    int bn = tid & 127, kh = tid >> 7;
    uint32_t a_r = wm * 64 + (lane & 15);
    uint32_t b_r = wn * 32 + (lane & 15);
    uint32_t chi = lane >> 4;

    float acc[4][4][4] = {};
    uint32_t rb[16];

    const int NS = F / KCH;   // 16
    {
        uint32_t SA = sbuf, SB = SA + DN_AST;
        #pragma unroll
        for (int q = 0; q < 8; q++)
            CP16(SA + sw256(crow, cbase + q), A + (size_t)crow * F + (cbase + q) * 8);
        CP_COMMIT();
        #pragma unroll
        for (int q = 0; q < 16; q++)
            rb[q] = packh2(W[(size_t)(kh * 32 + 2 * q) * H + bn], W[(size_t)(kh * 32 + 2 * q + 1) * H + bn]);
        #pragma unroll
        for (int c = 0; c < 4; c++)
            STS128(SB + sw256(bn, kh * 4 + c), rb[4*c], rb[4*c+1], rb[4*c+2], rb[4*c+3]);
        CP_WAIT0();
        __syncthreads();
    }

    for (int s = 0; s < NS; s++) {
        uint32_t SA = sbuf + (s & 1) * DN_STG, SB = SA + DN_AST;
        uint32_t SAn = sbuf + ((s + 1) & 1) * DN_STG, SBn = SAn + DN_AST;
        int k0 = (s + 1) * KCH;

        if (s + 1 < NS) {
            #pragma unroll
            for (int q = 0; q < 8; q++)
                CP16(SAn + sw256(crow, cbase + q), A + (size_t)crow * F + k0 + (cbase + q) * 8);
            CP_COMMIT();
            #pragma unroll
            for (int q = 0; q < 16; q++)
                rb[q] = packh2(W[(size_t)(k0 + kh * 32 + 2 * q) * H + bn], W[(size_t)(k0 + kh * 32 + 2 * q + 1) * H + bn]);
        }
        #pragma unroll
        for (int ks = 0; ks < 8; ks++) {
            uint32_t a[4][4], bq[2][4];
            #pragma unroll
            for (int i = 0; i < 4; i++)
                LDSM4(a[i][0], a[i][1], a[i][2], a[i][3], SA + sw256(a_r + i * 16, ks * 2 + chi));
            #pragma unroll
            for (int j = 0; j < 2; j++)
                LDSM4(bq[j][0], bq[j][1], bq[j][2], bq[j][3], SB + sw256(b_r + j * 16, ks * 2 + chi));
            #pragma unroll
            for (int i = 0; i < 4; i++)
                #pragma unroll
                for (int j4 = 0; j4 < 4; j4++)
                    MMA16(acc[i][j4], a[i], bq[j4 >> 1][j4 & 1], bq[j4 >> 1][(j4 & 1) + 2]);
        }
        if (s + 1 < NS) {
            #pragma unroll
            for (int c = 0; c < 4; c++)
                STS128(SBn + sw256(bn, kh * 4 + c), rb[4*c], rb[4*c+1], rb[4*c+2], rb[4*c+3]);
        }
        CP_WAIT0();
        __syncthreads();
    }

    float* Y = g_y + (size_t)e * CAP * H;
    int r0 = m0 + wm * 64 + (lane >> 2);
    int c0 = n0 + wn * 32 + (lane & 3) * 2;
    #pragma unroll
    for (int i = 0; i < 4; i++) {
        #pragma unroll
        for (int j = 0; j < 4; j++) {
            int r = r0 + i * 16, c = c0 + j * 8;
            if (r < cnt)
                *(float2*)(Y + (size_t)r * H + c) = make_float2(acc[i][j][0], acc[i][j][1]);
            if (r + 8 < cnt)
                *(float2*)(Y + (size_t)(r + 8) * H + c) = make_float2(acc[i][j][2], acc[i][j][3]);
        }
    }
}

// ---------------- combine ----------------
__global__ void combine_kernel(float* __restrict__ out) {
    int t = blockIdx.x;
    int i0 = 2 * t, i1 = 2 * t + 1;
    int e0 = g_route_e[i0], e1 = g_route_e[i1];
    int k0 = g_route_keep[i0], k1 = g_route_keep[i1];
    int p0 = k0 ? g_route_pos[i0] : 0;
    int p1 = k1 ? g_route_pos[i1] : 0;
    float w0 = k0 ? g_route_w[i0] : 0.f;
    float w1 = k1 ? g_route_w[i1] : 0.f;
    const float* y0 = g_y + ((size_t)e0 * CAP + p0) * H;
    const float* y1 = g_y + ((size_t)e1 * CAP + p1) * H;
    float* o = out + (size_t)t * H;
    int h = threadIdx.x * 4;
    float4 a = *(const float4*)(y0 + h);
    float4 b = *(const float4*)(y1 + h);
    float4 r;
    r.x = w0 * a.x + w1 * b.x;
    r.y = w0 * a.y + w1 * b.y;
    r.z = w0 * a.z + w1 * b.z;
    r.w = w0 * a.w + w1 * b.w;
    *(float4*)(o + h) = r;
}

// ---------------- aux loss ----------------
__global__ void aux_kernel(float* __restrict__ out_aux) {
    int e = threadIdx.x >> 5, lane = threadIdx.x & 31;
    float s = 0.f; int c = 0;
    for (int t = lane; t < T; t += 32) {
        s += g_probs[(size_t)t * E + e];
        c += (g_top1[t] == e) ? 1 : 0;
    }
    #pragma unroll
    for (int o = 16; o; o >>= 1) {
        s += __shfl_xor_sync(0xffffffffu, s, o);
        c += __shfl_xor_sync(0xffffffffu, c, o);
    }
    __shared__ float part[E];
    if (lane == 0) part[e] = (s / (float)T) * ((float)c / (float)T);
    __syncthreads();
    if (threadIdx.x == 0) {
        float a = 0.f;
        for (int i = 0; i < E; i++) a += part[i];
        *out_aux = a * (float)E * AUX_COEF;
    }
}

// ---------------- launch ----------------
extern "C" void kernel_launch(void* const* d_in, const int* in_sizes, int n_in,
                              void* d_out, int out_size) {
    const float* x  = (const float*)d_in[0];
    const float* Wr = (const float*)d_in[1];
    const float* br = (const float*)d_in[2];
    const float* Wg = (const float*)d_in[3];
    const float* Wu = (const float*)d_in[4];
    const float* Wd = (const float*)d_in[5];
    float* out = (float*)d_out;

    int smem = 2 * GU_STG + 128;   // 192KB + pad (same for both kernels)
    cudaFuncSetAttribute(gu_mma, cudaFuncAttributeMaxDynamicSharedMemorySize, smem);
    cudaFuncSetAttribute(down_mma, cudaFuncAttributeMaxDynamicSharedMemorySize, smem);

    router_kernel<<<T, 256>>>(x, Wr, br);
    dispatch_kernel<<<1, 1024>>>();
    gather_kernel<<<T * KSEL, 256>>>(x);

    dim3 gu_grid(F / 128, CAP / 128, E);
    gu_mma<<<gu_grid, 512, smem>>>(Wg, Wu);

    dim3 dn_grid(H / 128, CAP / 256, E);
    down_mma<<<dn_grid, 512, smem>>>(Wd);

    combine_kernel<<<T, 256>>>(out);

    if (out_size > T * H)
        aux_kernel<<<1, 1024>>>(out + (size_t)T * H);
}

// round 9
// speedup vs baseline: 1.2985x; 1.0598x over previous
#include <cuda_runtime.h>
#include <cuda_fp16.h>
#include <cstdint>

// ---------------- static problem config ----------------
#define T 4096
#define H 1024
#define F 2048
#define E 32
#define KSEL 2
#define CAP 512
#define AUX_COEF 0.01f

// ---------------- device scratch ----------------
__device__ float  g_probs[T * E];
__device__ int    g_top1[T];
__device__ int    g_route_e[T * KSEL];
__device__ float  g_route_w[T * KSEL];
__device__ int    g_route_pos[T * KSEL];
__device__ int    g_route_keep[T * KSEL];
__device__ int    g_count[E];
__device__ __half g_buf[(size_t)E * CAP * H];
__device__ __half g_hid[(size_t)E * CAP * F];
__device__ float  g_y[(size_t)E * CAP * H];

// ---------------- helpers ----------------
__device__ __forceinline__ uint32_t smem_u32(const void* p) {
    uint32_t a;
    asm("{ .reg .u64 t; cvta.to.shared.u64 t, %1; cvt.u32.u64 %0, t; }" : "=r"(a) : "l"(p));
    return a;
}
__device__ __forceinline__ uint32_t packh2(float lo, float hi) {
    __half2 h = __floats2half2_rn(lo, hi);
    return *(uint32_t*)&h;
}
#define STS128(ad, a0, a1, a2, a3) \
    asm volatile("st.shared.v4.b32 [%0], {%1,%2,%3,%4};" :: "r"(ad), "r"(a0), "r"(a1), "r"(a2), "r"(a3) : "memory")
#define LDSM4(r0, r1, r2, r3, ad) \
    asm volatile("ldmatrix.sync.aligned.m8n8.x4.shared.b16 {%0,%1,%2,%3}, [%4];" \
        : "=r"(r0), "=r"(r1), "=r"(r2), "=r"(r3) : "r"(ad))
#define MMA16(d, a, b0v, b1v) \
    asm volatile("mma.sync.aligned.m16n8k16.row.col.f32.f16.f16.f32 " \
        "{%0,%1,%2,%3}, {%4,%5,%6,%7}, {%8,%9}, {%0,%1,%2,%3};" \
        : "+f"(d[0]), "+f"(d[1]), "+f"(d[2]), "+f"(d[3]) \
        : "r"(a[0]), "r"(a[1]), "r"(a[2]), "r"(a[3]), "r"(b0v), "r"(b1v))
#define CP16(dst, src) \
    asm volatile("cp.async.cg.shared.global [%0], [%1], 16;" :: "r"(dst), "l"(src) : "memory")
#define CP_COMMIT() asm volatile("cp.async.commit_group;" ::: "memory")
#define CP_WAIT0()  asm volatile("cp.async.wait_group 0;" ::: "memory")

// 256B-row swizzle: 16 chunks of 16B; phys chunk = c ^ (row & 7) (bit3 preserved)
__device__ __forceinline__ uint32_t sw256(uint32_t row, uint32_t c) {
    return row * 256 + ((c ^ (row & 7)) * 16);
}

// ---------------- router: 16 tokens/block, Wr streamed once per block ----------------
#define RT 16
__global__ void __launch_bounds__(256) router_kernel(const float* __restrict__ x,
                                                     const float* __restrict__ Wr,
                                                     const float* __restrict__ br) {
    extern __shared__ float xs[];          // RT * H floats (64KB)
    __shared__ float sl[RT * E];
    int tid = threadIdx.x;
    int tb = blockIdx.x * RT;

    // load 16 tokens (flat float4 copy)
    const float4* xp = (const float4*)x + (size_t)tb * (H / 4);
    float4* xsp = (float4*)xs;
    #pragma unroll
    for (int i = 0; i < RT; i++)
        xsp[tid + i * 256] = xp[tid + i * 256];
    __syncthreads();

    // dot products: thread (e, r) covers h-slice r*4 within 32-h chunks
    int e = tid >> 3, r = tid & 7;
    float acc[RT];
    #pragma unroll
    for (int t = 0; t < RT; t++) acc[t] = 0.f;
    const float4* wp = (const float4*)(Wr + (size_t)e * H) + r;
    #pragma unroll 4
    for (int h8 = 0; h8 < H / 32; h8++) {
        float4 w = wp[h8 * 8];
        #pragma unroll
        for (int t = 0; t < RT; t++) {
            float4 xv = xsp[t * 256 + h8 * 8 + r];
            acc[t] += w.x * xv.x + w.y * xv.y + w.z * xv.z + w.w * xv.w;
        }
    }
    float be = br[e];
    #pragma unroll
    for (int t = 0; t < RT; t++) {
        float a = acc[t];
        a += __shfl_down_sync(0xffffffffu, a, 4, 8);
        a += __shfl_down_sync(0xffffffffu, a, 2, 8);
        a += __shfl_down_sync(0xffffffffu, a, 1, 8);
        if (r == 0) sl[t * E + e] = a + be;
    }
    __syncthreads();

    // softmax + top2 per token: warp w handles tokens 2w, 2w+1
    int wid = tid >> 5, lane = tid & 31;
    #pragma unroll
    for (int tt = 0; tt < 2; tt++) {
        int tl = wid * 2 + tt;
        int t = tb + tl;
        float l = sl[tl * E + lane];
        float m = l;
        #pragma unroll
        for (int o = 16; o; o >>= 1) m = fmaxf(m, __shfl_xor_sync(0xffffffffu, m, o));
        float p = __expf(l - m);
        float s = p;
        #pragma unroll
        for (int o = 16; o; o >>= 1) s += __shfl_xor_sync(0xffffffffu, s, o);
        p = p / s;
        g_probs[(size_t)t * E + lane] = p;
        float p1 = p; int i1 = lane;
        #pragma unroll
        for (int o = 16; o; o >>= 1) {
            float op = __shfl_xor_sync(0xffffffffu, p1, o);
            int   oi = __shfl_xor_sync(0xffffffffu, i1, o);
            if (op > p1 || (op == p1 && oi < i1)) { p1 = op; i1 = oi; }
        }
        float pm = (lane == i1) ? -1.f : p;
        float p2 = pm; int i2 = lane;
        #pragma unroll
        for (int o = 16; o; o >>= 1) {
            float op = __shfl_xor_sync(0xffffffffu, p2, o);
            int   oi = __shfl_xor_sync(0xffffffffu, i2, o);
            if (op > p2 || (op == p2 && oi < i2)) { p2 = op; i2 = oi; }
        }
        if (lane == 0) {
            g_top1[t] = i1;
            float mx = fmaxf(p1, p2);
            float e1 = __expf(p1 - mx), e2 = __expf(p2 - mx);
            float inv = 1.f / (e1 + e2);
            g_route_e[2 * t]     = i1; g_route_w[2 * t]     = e1 * inv;
            g_route_e[2 * t + 1] = i2; g_route_w[2 * t + 1] = e2 * inv;
        }
    }
}

// ---------------- dispatch ----------------
__global__ void dispatch_kernel() {
    __shared__ int se[T * KSEL];
    int tid = threadIdx.x;
    for (int i = tid; i < T * KSEL; i += 1024) se[i] = g_route_e[i];
    __syncthreads();
    int warp = tid >> 5, lane = tid & 31;
    int base = 0;
    for (int c = 0; c < T * KSEL; c += 32) {
        int e = se[c + lane];
        unsigned m = __ballot_sync(0xffffffffu, e == warp);
        if (e == warp) {
            int pos = base + __popc(m & ((1u << lane) - 1u));
            g_route_pos[c + lane]  = pos;
            g_route_keep[c + lane] = (pos < CAP) ? 1 : 0;
        }
        base += __popc(m);
    }
    if (lane == 0) g_count[warp] = (base < CAP) ? base : CAP;
}

// ---------------- gather ----------------
__global__ void gather_kernel(const float* __restrict__ x) {
    int i = blockIdx.x;
    if (!g_route_keep[i]) return;
    int t = i >> 1;
    int e = g_route_e[i], pos = g_route_pos[i];
    __half* dst = g_buf + ((size_t)e * CAP + pos) * H;
    const float* src = x + (size_t)t * H;
    int h = threadIdx.x * 4;
    float4 v = *(const float4*)(src + h);
    uint2 o;
    o.x = packh2(v.x, v.y);
    o.y = packh2(v.z, v.w);
    *(uint2*)(dst + h) = o;
}

// ---------------- fused gate/up GEMM + SwiGLU (fp16 mma.sync) ----------------
#define KCH 128
#define GU_AST (128 * 256)
#define GU_STG (3 * GU_AST)          // 96KB/stage
#define DN_AST (256 * 256)
#define DN_BST (128 * 256)
#define DN_STG (DN_AST + DN_BST)     // 96KB/stage

__global__ void __launch_bounds__(512, 1) gu_mma(const float* __restrict__ Wg,
                                                 const float* __restrict__ Wu) {
    extern __shared__ char smem[];
    int e = blockIdx.z, cnt = g_count[e];
    int m0 = blockIdx.y * 128;
    if (m0 >= cnt) return;
    int n0 = blockIdx.x * 128;
    uint32_t sbuf = (smem_u32(smem) + 127u) & ~127u;

    int tid = threadIdx.x, lane = tid & 31, wid = tid >> 5;
    int wm = wid >> 2, wn = wid & 3;

    const __half* A = g_buf + (size_t)e * CAP * H + (size_t)m0 * H;
    const float* G = Wg + (size_t)e * H * F + n0;
    const float* U = Wu + (size_t)e * H * F + n0;

    int crow = tid >> 2, cbase = (tid & 3) * 4;
    int bn = tid & 127, kh = tid >> 7;
    uint32_t a_r = wm * 32 + (lane & 15);
    uint32_t b_r = wn * 32 + (lane & 15);
    uint32_t chi = lane >> 4;

    float accG[2][4][4] = {};
    float accU[2][4][4] = {};
    uint32_t rb[16];

    const int NS = H / KCH;   // 8
    {
        uint32_t SA = sbuf, SBG = SA + GU_AST, SBU = SBG + GU_AST;
        #pragma unroll
        for (int q = 0; q < 4; q++)
            CP16(SA + sw256(crow, cbase + q), A + (size_t)crow * H + (cbase + q) * 8);
        CP_COMMIT();
        #pragma unroll
        for (int q = 0; q < 16; q++)
            rb[q] = packh2(G[(size_t)(kh * 32 + 2 * q) * F + bn], G[(size_t)(kh * 32 + 2 * q + 1) * F + bn]);
        #pragma unroll
        for (int c = 0; c < 4; c++)
            STS128(SBG + sw256(bn, kh * 4 + c), rb[4*c], rb[4*c+1], rb[4*c+2], rb[4*c+3]);
        #pragma unroll
        for (int q = 0; q < 16; q++)
            rb[q] = packh2(U[(size_t)(kh * 32 + 2 * q) * F + bn], U[(size_t)(kh * 32 + 2 * q + 1) * F + bn]);
        #pragma unroll
        for (int c = 0; c < 4; c++)
            STS128(SBU + sw256(bn, kh * 4 + c), rb[4*c], rb[4*c+1], rb[4*c+2], rb[4*c+3]);
        CP_WAIT0();
        __syncthreads();
    }

    #pragma unroll 2
    for (int s = 0; s < NS; s++) {
        uint32_t SA = sbuf + (s & 1) * GU_STG;
        uint32_t SBG = SA + GU_AST, SBU = SBG + GU_AST;
        uint32_t SAn = sbuf + ((s + 1) & 1) * GU_STG;
        uint32_t SBGn = SAn + GU_AST, SBUn = SBGn + GU_AST;
        int k0 = (s + 1) * KCH;

        if (s + 1 < NS) {
            #pragma unroll
            for (int q = 0; q < 4; q++)
                CP16(SAn + sw256(crow, cbase + q), A + (size_t)crow * H + k0 + (cbase + q) * 8);
            CP_COMMIT();
            #pragma unroll
            for (int q = 0; q < 16; q++)
                rb[q] = packh2(G[(size_t)(k0 + kh * 32 + 2 * q) * F + bn], G[(size_t)(k0 + kh * 32 + 2 * q + 1) * F + bn]);
        }
        #pragma unroll
        for (int ks = 0; ks < 4; ks++) {
            uint32_t a[2][4], bg[2][4], bu[2][4];
            #pragma unroll
            for (int i = 0; i < 2; i++)
                LDSM4(a[i][0], a[i][1], a[i][2], a[i][3], SA + sw256(a_r + i * 16, ks * 2 + chi));
            #pragma unroll
            for (int j = 0; j < 2; j++) {
                LDSM4(bg[j][0], bg[j][1], bg[j][2], bg[j][3], SBG + sw256(b_r + j * 16, ks * 2 + chi));
                LDSM4(bu[j][0], bu[j][1], bu[j][2], bu[j][3], SBU + sw256(b_r + j * 16, ks * 2 + chi));
            }
            #pragma unroll
            for (int i = 0; i < 2; i++)
                #pragma unroll
                for (int j4 = 0; j4 < 4; j4++) {
                    MMA16(accG[i][j4], a[i], bg[j4 >> 1][j4 & 1], bg[j4 >> 1][(j4 & 1) + 2]);
                    MMA16(accU[i][j4], a[i], bu[j4 >> 1][j4 & 1], bu[j4 >> 1][(j4 & 1) + 2]);
                }
        }
        if (s + 1 < NS) {
            #pragma unroll
            for (int c = 0; c < 4; c++)
                STS128(SBGn + sw256(bn, kh * 4 + c), rb[4*c], rb[4*c+1], rb[4*c+2], rb[4*c+3]);
            #pragma unroll
            for (int q = 0; q < 16; q++)
                rb[q] = packh2(U[(size_t)(k0 + kh * 32 + 2 * q) * F + bn], U[(size_t)(k0 + kh * 32 + 2 * q + 1) * F + bn]);
        }
        #pragma unroll
        for (int ks = 4; ks < 8; ks++) {
            uint32_t a[2][4], bg[2][4], bu[2][4];
            #pragma unroll
            for (int i = 0; i < 2; i++)
                LDSM4(a[i][0], a[i][1], a[i][2], a[i][3], SA + sw256(a_r + i * 16, ks * 2 + chi));
            #pragma unroll
            for (int j = 0; j < 2; j++) {
                LDSM4(bg[j][0], bg[j][1], bg[j][2], bg[j][3], SBG + sw256(b_r + j * 16, ks * 2 + chi));
                LDSM4(bu[j][0], bu[j][1], bu[j][2], bu[j][3], SBU + sw256(b_r + j * 16, ks * 2 + chi));
            }
            #pragma unroll
            for (int i = 0; i < 2; i++)
                #pragma unroll
                for (int j4 = 0; j4 < 4; j4++) {
                    MMA16(accG[i][j4], a[i], bg[j4 >> 1][j4 & 1], bg[j4 >> 1][(j4 & 1) + 2]);
                    MMA16(accU[i][j4], a[i], bu[j4 >> 1][j4 & 1], bu[j4 >> 1][(j4 & 1) + 2]);
                }
        }
        if (s + 1 < NS) {
            #pragma unroll
            for (int c = 0; c < 4; c++)
                STS128(SBUn + sw256(bn, kh * 4 + c), rb[4*c], rb[4*c+1], rb[4*c+2], rb[4*c+3]);
        }
        CP_WAIT0();
        __syncthreads();
    }

    __half* Hd = g_hid + (size_t)e * CAP * F;
    int r0 = m0 + wm * 32 + (lane >> 2);
    int c0 = n0 + wn * 32 + (lane & 3) * 2;
    #pragma unroll
    for (int i = 0; i < 2; i++) {
        #pragma unroll
        for (int j = 0; j < 4; j++) {
            int r = r0 + i * 16, c = c0 + j * 8;
            if (r < cnt) {
                float g0 = accG[i][j][0], g1 = accG[i][j][1];
                *(uint32_t*)(Hd + (size_t)r * F + c) =
                    packh2(g0 / (1.f + __expf(-g0)) * accU[i][j][0],
                           g1 / (1.f + __expf(-g1)) * accU[i][j][1]);
            }
            if (r + 8 < cnt) {
                float g2 = accG[i][j][2], g3 = accG[i][j][3];
                *(uint32_t*)(Hd + (size_t)(r + 8) * F + c) =
                    packh2(g2 / (1.f + __expf(-g2)) * accU[i][j][2],
                           g3 / (1.f + __expf(-g3)) * accU[i][j][3]);
            }
        }
    }
}

// ---------------- down GEMM ----------------
__global__ void __launch_bounds__(512, 1) down_mma(const float* __restrict__ Wd) {
    extern __shared__ char smem[];
    int e = blockIdx.z, cnt = g_count[e];
    int m0 = blockIdx.y * 256;
    if (m0 >= cnt) return;
    int n0 = blockIdx.x * 128;
    uint32_t sbuf = (smem_u32(smem) + 127u) & ~127u;

    int tid = threadIdx.x, lane = tid & 31, wid = tid >> 5;
    int wm = wid >> 2, wn = wid & 3;

    const __half* A = g_hid + ((size_t)e * CAP + m0) * F;
    const float*  W = Wd + (size_t)e * F * H + n0;

    int crow = tid >> 1, cbase = (tid & 1) * 8;
    int bn = tid & 127, kh = tid >> 7;
    uint32_t a_r = wm * 64 + (lane & 15);
    uint32_t b_r = wn * 32 + (lane & 15);
    uint32_t chi = lane >> 4;

    float acc[4][4][4] = {};
    uint32_t rb[16];

    const int NS = F / KCH;   // 16
    {
        uint32_t SA = sbuf, SB = SA + DN_AST;
        #pragma unroll
        for (int q = 0; q < 8; q++)
            CP16(SA + sw256(crow, cbase + q), A + (size_t)crow * F + (cbase + q) * 8);
        CP_COMMIT();
        #pragma unroll
        for (int q = 0; q < 16; q++)
            rb[q] = packh2(W[(size_t)(kh * 32 + 2 * q) * H + bn], W[(size_t)(kh * 32 + 2 * q + 1) * H + bn]);
        #pragma unroll
        for (int c = 0; c < 4; c++)
            STS128(SB + sw256(bn, kh * 4 + c), rb[4*c], rb[4*c+1], rb[4*c+2], rb[4*c+3]);
        CP_WAIT0();
        __syncthreads();
    }

    #pragma unroll 2
    for (int s = 0; s < NS; s++) {
        uint32_t SA = sbuf + (s & 1) * DN_STG, SB = SA + DN_AST;
        uint32_t SAn = sbuf + ((s + 1) & 1) * DN_STG, SBn = SAn + DN_AST;
        int k0 = (s + 1) * KCH;

        if (s + 1 < NS) {
            #pragma unroll
            for (int q = 0; q < 8; q++)
                CP16(SAn + sw256(crow, cbase + q), A + (size_t)crow * F + k0 + (cbase + q) * 8);
            CP_COMMIT();
            #pragma unroll
            for (int q = 0; q < 16; q++)
                rb[q] = packh2(W[(size_t)(k0 + kh * 32 + 2 * q) * H + bn], W[(size_t)(k0 + kh * 32 + 2 * q + 1) * H + bn]);
        }
        #pragma unroll
        for (int ks = 0; ks < 8; ks++) {
            uint32_t a[4][4], bq[2][4];
            #pragma unroll
            for (int i = 0; i < 4; i++)
                LDSM4(a[i][0], a[i][1], a[i][2], a[i][3], SA + sw256(a_r + i * 16, ks * 2 + chi));
            #pragma unroll
            for (int j = 0; j < 2; j++)
                LDSM4(bq[j][0], bq[j][1], bq[j][2], bq[j][3], SB + sw256(b_r + j * 16, ks * 2 + chi));
            #pragma unroll
            for (int i = 0; i < 4; i++)
                #pragma unroll
                for (int j4 = 0; j4 < 4; j4++)
                    MMA16(acc[i][j4], a[i], bq[j4 >> 1][j4 & 1], bq[j4 >> 1][(j4 & 1) + 2]);
        }
        if (s + 1 < NS) {
            #pragma unroll
            for (int c = 0; c < 4; c++)
                STS128(SBn + sw256(bn, kh * 4 + c), rb[4*c], rb[4*c+1], rb[4*c+2], rb[4*c+3]);
        }
        CP_WAIT0();
        __syncthreads();
    }

    float* Y = g_y + (size_t)e * CAP * H;
    int r0 = m0 + wm * 64 + (lane >> 2);
    int c0 = n0 + wn * 32 + (lane & 3) * 2;
    #pragma unroll
    for (int i = 0; i < 4; i++) {
        #pragma unroll
        for (int j = 0; j < 4; j++) {
            int r = r0 + i * 16, c = c0 + j * 8;
            if (r < cnt)
                *(float2*)(Y + (size_t)r * H + c) = make_float2(acc[i][j][0], acc[i][j][1]);
            if (r + 8 < cnt)
                *(float2*)(Y + (size_t)(r + 8) * H + c) = make_float2(acc[i][j][2], acc[i][j][3]);
        }
    }
}

// ---------------- combine ----------------
__global__ void combine_kernel(float* __restrict__ out) {
    int t = blockIdx.x;
    int i0 = 2 * t, i1 = 2 * t + 1;
    int e0 = g_route_e[i0], e1 = g_route_e[i1];
    int k0 = g_route_keep[i0], k1 = g_route_keep[i1];
    int p0 = k0 ? g_route_pos[i0] : 0;
    int p1 = k1 ? g_route_pos[i1] : 0;
    float w0 = k0 ? g_route_w[i0] : 0.f;
    float w1 = k1 ? g_route_w[i1] : 0.f;
    const float* y0 = g_y + ((size_t)e0 * CAP + p0) * H;
    const float* y1 = g_y + ((size_t)e1 * CAP + p1) * H;
    float* o = out + (size_t)t * H;
    int h = threadIdx.x * 4;
    float4 a = *(const float4*)(y0 + h);
    float4 b = *(const float4*)(y1 + h);
    float4 r;
    r.x = w0 * a.x + w1 * b.x;
    r.y = w0 * a.y + w1 * b.y;
    r.z = w0 * a.z + w1 * b.z;
    r.w = w0 * a.w + w1 * b.w;
    *(float4*)(o + h) = r;
}

// ---------------- aux loss ----------------
__global__ void aux_kernel(float* __restrict__ out_aux) {
    int e = threadIdx.x >> 5, lane = threadIdx.x & 31;
    float s = 0.f; int c = 0;
    for (int t = lane; t < T; t += 32) {
        s += g_probs[(size_t)t * E + e];
        c += (g_top1[t] == e) ? 1 : 0;
    }
    #pragma unroll
    for (int o = 16; o; o >>= 1) {
        s += __shfl_xor_sync(0xffffffffu, s, o);
        c += __shfl_xor_sync(0xffffffffu, c, o);
    }
    __shared__ float part[E];
    if (lane == 0) part[e] = (s / (float)T) * ((float)c / (float)T);
    __syncthreads();
    if (threadIdx.x == 0) {
        float a = 0.f;
        for (int i = 0; i < E; i++) a += part[i];
        *out_aux = a * (float)E * AUX_COEF;
    }
}

// ---------------- launch ----------------
extern "C" void kernel_launch(void* const* d_in, const int* in_sizes, int n_in,
                              void* d_out, int out_size) {
    const float* x  = (const float*)d_in[0];
    const float* Wr = (const float*)d_in[1];
    const float* br = (const float*)d_in[2];
    const float* Wg = (const float*)d_in[3];
    const float* Wu = (const float*)d_in[4];
    const float* Wd = (const float*)d_in[5];
    float* out = (float*)d_out;

    int smem = 2 * GU_STG + 128;
    int rsm = RT * H * 4;
    cudaFuncSetAttribute(gu_mma, cudaFuncAttributeMaxDynamicSharedMemorySize, smem);
    cudaFuncSetAttribute(down_mma, cudaFuncAttributeMaxDynamicSharedMemorySize, smem);
    cudaFuncSetAttribute(router_kernel, cudaFuncAttributeMaxDynamicSharedMemorySize, rsm);

    router_kernel<<<T / RT, 256, rsm>>>(x, Wr, br);
    dispatch_kernel<<<1, 1024>>>();
    gather_kernel<<<T * KSEL, 256>>>(x);

    dim3 gu_grid(F / 128, CAP / 128, E);
    gu_mma<<<gu_grid, 512, smem>>>(Wg, Wu);

    dim3 dn_grid(H / 128, CAP / 256, E);
    down_mma<<<dn_grid, 512, smem>>>(Wd);

    combine_kernel<<<T, 256>>>(out);

    if (out_size > T * H)
        aux_kernel<<<1, 1024>>>(out + (size_t)T * H);
}